// round 16
// baseline (speedup 1.0000x reference)
#include <cuda_runtime.h>
#include <cuda_fp16.h>
#include <cstdint>

// Problem constants (fixed by the dataset)
#define NB   8
#define LQ   1024
#define NQ   (NB*LQ)        // 8192
#define DM   256
#define DFF  1024
#define NH   8
#define HD   32
#define NL   4
#define NP   4
#define LIN  43520
#define NV   (NB*LIN)       // 348160

// -------------------- scratch (device globals) -------------------------------
__device__ float  g_q   [(size_t)NQ*DM];
__device__ __half g_value[(size_t)NV*DM];      // fp16 value (178 MB)
__device__ float  g_off [(size_t)NQ*NH*NL*NP*3];
__device__ float  g_attn[(size_t)NQ*NH*NL*NP];
__device__ float  g_acc [(size_t)NQ*DM];
__device__ float  g_t2  [(size_t)NQ*DM];
__device__ float  g_x   [(size_t)NQ*DM];
__device__ float  g_ff1 [(size_t)NQ*DFF];
__device__ float  g_y   [(size_t)NQ*DM];
__device__ __half g_wh  [786432];   // permuted fp16 weights

#define WT_V 0
#define WT_O 65536
#define WT_A 163840
#define WT_P 196608
#define WT_1 262144
#define WT_2 524288

// -------------------- smem layout: 128x128 tile, 3 stages ----------------------
// A: fp32, 128 rows x 32 k, stride 36 floats. B: fp16, 128 n-rows x 32 k', dense.
#define A_STRIDE 36
#define ABUF (128 * A_STRIDE)              // 4608 floats / stage
#define NSTAGE 3
#define A_BYTES (NSTAGE * ABUF * 4)        // 55296
#define B_STG_BYTES (128 * 32 * 2)         // 8192 / stage
#define SMEM_BYTES (A_BYTES + NSTAGE * B_STG_BYTES)   // 79872

__device__ __forceinline__ uint32_t smem_to_u32(const void* p) {
    uint32_t a;
    asm("{ .reg .u64 t; cvta.to.shared.u64 t, %1; cvt.u32.u64 %0, t; }" : "=r"(a) : "l"(p));
    return a;
}

#define CP_ASYNC16(saddr, gaddr) \
    asm volatile("cp.async.cg.shared.global [%0], [%1], 16;" :: "r"(saddr), "l"(gaddr))
#define CP_COMMIT() asm volatile("cp.async.commit_group;" ::: "memory")
#define CP_WAIT1()  asm volatile("cp.async.wait_group 1;" ::: "memory")
#define CP_WAIT0()  asm volatile("cp.async.wait_group 0;" ::: "memory")

#define MMA_F16(d, a, b0, b1) \
    asm volatile("mma.sync.aligned.m16n8k16.row.col.f32.f16.f16.f32 " \
        "{%0,%1,%2,%3}, {%4,%5,%6,%7}, {%8,%9}, {%0,%1,%2,%3};" \
        : "+f"((d)[0]), "+f"((d)[1]), "+f"((d)[2]), "+f"((d)[3]) \
        : "r"((a)[0]), "r"((a)[1]), "r"((a)[2]), "r"((a)[3]), "r"(b0), "r"(b1))

__device__ __forceinline__ uint32_t f22h2(float2 v) {
    __half2 h = __float22half2_rn(v);
    return *reinterpret_cast<uint32_t*>(&h);
}

// -------------------- weight permute (fp32 -> fp16, m16n8k16 B order) ----------
// Within each 32-k chunk, position p = tg*8 + u maps to
// k = 2*tg + (u&1) + 8*((u>>1)&1) + 16*(u>>2)
// so one LDS.128 at half-offset tg*8 yields {b0,b1} for both k16 steps.
__global__ void permute_wh(const float* __restrict__ W, __half* __restrict__ Wp,
                           int K, int N)
{
    int i = blockIdx.x * 256 + threadIdx.x;
    if (i >= N * K) return;
    int n = i / K, r = i - n * K;
    int kc = r >> 5, p = r & 31;
    int tg = p >> 3, u = p & 7;
    int k = kc * 32 + 2 * tg + (u & 1) + 8 * ((u >> 1) & 1) + 16 * (u >> 2);
    Wp[i] = __float2half(W[(size_t)k * N + n]);
}

// -------------------- FP16 tensor-core GEMM, 128x128 tile, 3-stage -------------
// C[M,N] = A[M,K] @ W[K,N] + bias (+resid) (relu?) (mask -> zero row)
// OUTHALF: C is __half*, else float*. A fp32, Wp permuted fp16.
// Grid: (N/128, M/128). 256 threads. K % 32 == 0, K >= 64.
template<int RELU, int OUTHALF>
__global__ __launch_bounds__(256, 2)
void mma_gemm(const float* __restrict__ A, const __half* __restrict__ Wp,
              const float* __restrict__ bias, const float* __restrict__ resid,
              const unsigned char* __restrict__ mask,
              void* __restrict__ Cv, int M, int N, int K)
{
    extern __shared__ float sm[];
    uint32_t sb = smem_to_u32(sm);
    const int tid  = threadIdx.x;
    const int wid  = tid >> 5, lane = tid & 31;
    const int g    = lane >> 2, tg = lane & 3;
    const int mw   = wid & 3,  nw = wid >> 2;   // 4 m-warps x 2 n-warps
    const int m0   = blockIdx.y * 128;
    const int n0   = blockIdx.x * 128;
    const int nK   = K >> 5;

    float d[2][8][4];
#pragma unroll
    for (int mi = 0; mi < 2; mi++)
#pragma unroll
        for (int nj = 0; nj < 8; nj++)
#pragma unroll
            for (int r = 0; r < 4; r++) d[mi][nj][r] = 0.f;

    auto load_chunk = [&](int kc, int stage) {
        const char* Ag = (const char*)(A + (size_t)m0 * K + (size_t)kc * 32);
#pragma unroll
        for (int i = 0; i < 4; i++) {
            int u = tid + i * 256;
            int row = u >> 3, seg = u & 7;
            uint32_t sa = sb + (uint32_t)(stage * ABUF + row * A_STRIDE + seg * 4) * 4;
            CP_ASYNC16(sa, Ag + ((size_t)row * K + seg * 4) * 4);
        }
        const char* Wg = (const char*)(Wp + (size_t)n0 * K + (size_t)kc * 32);
#pragma unroll
        for (int i = 0; i < 2; i++) {
            int u = tid + i * 256;
            int row = u >> 2, seg = u & 3;
            uint32_t sa = sb + (uint32_t)A_BYTES + (uint32_t)(stage * B_STG_BYTES + row * 64 + seg * 16);
            CP_ASYNC16(sa, Wg + (size_t)row * K * 2 + seg * 16);
        }
        CP_COMMIT();
    };

    load_chunk(0, 0);
    load_chunk(1, 1);

    int stage = 0;
    for (int kc = 0; kc < nK; kc++) {
        if (kc == nK - 1) { CP_WAIT0(); } else { CP_WAIT1(); }
        __syncthreads();
        // prefetch chunk kc+2 into the stage last read at kc-1 (all warps past it)
        if (kc + 2 < nK) {
            int ns = stage + 2; if (ns >= NSTAGE) ns -= NSTAGE;
            load_chunk(kc + 2, ns);
        }

        const float* Asb = sm + stage * ABUF;
        const __half* Bsb = reinterpret_cast<const __half*>(
            (const char*)sm + A_BYTES + stage * B_STG_BYTES);

        // B fragments: one LDS.128 per nj covers both k16 steps
        // .x = b0(ks0), .y = b1(ks0), .z = b0(ks1), .w = b1(ks1)
        uint4 bq[8];
#pragma unroll
        for (int nj = 0; nj < 8; nj++)
            bq[nj] = *reinterpret_cast<const uint4*>(
                Bsb + (nw * 64 + nj * 8 + g) * 32 + tg * 8);

#pragma unroll
        for (int ks = 0; ks < 2; ks++) {
            uint32_t a[2][4];
#pragma unroll
            for (int mi = 0; mi < 2; mi++) {
                const float* ap = Asb + (mw * 32 + mi * 16 + g) * A_STRIDE + ks * 16 + 2 * tg;
                a[mi][0] = f22h2(*reinterpret_cast<const float2*>(ap));
                a[mi][1] = f22h2(*reinterpret_cast<const float2*>(ap + 8 * A_STRIDE));
                a[mi][2] = f22h2(*reinterpret_cast<const float2*>(ap + 8));
                a[mi][3] = f22h2(*reinterpret_cast<const float2*>(ap + 8 * A_STRIDE + 8));
            }
#pragma unroll
            for (int nj = 0; nj < 8; nj++) {
                uint32_t b0 = ks ? bq[nj].z : bq[nj].x;
                uint32_t b1 = ks ? bq[nj].w : bq[nj].y;
                MMA_F16(d[0][nj], a[0], b0, b1);
                MMA_F16(d[1][nj], a[1], b0, b1);
            }
        }
        stage = (stage + 1 == NSTAGE) ? 0 : stage + 1;
    }

    // ---- epilogue ----
#pragma unroll
    for (int mi = 0; mi < 2; mi++) {
#pragma unroll
        for (int half = 0; half < 2; half++) {
            const int row = m0 + mw * 32 + mi * 16 + g + half * 8;
            const bool mz = (mask != nullptr) && mask[row];
            const float* rrow = resid ? (resid + (size_t)row * N) : nullptr;
#pragma unroll
            for (int nj = 0; nj < 8; nj++) {
                const int col = n0 + nw * 64 + nj * 8 + 2 * tg;
                float2 o;
                o.x = d[mi][nj][half * 2 + 0] + bias[col];
                o.y = d[mi][nj][half * 2 + 1] + bias[col + 1];
                if (rrow) {
                    float2 rv = *reinterpret_cast<const float2*>(rrow + col);
                    o.x += rv.x; o.y += rv.y;
                }
                if (RELU) { o.x = fmaxf(o.x, 0.f); o.y = fmaxf(o.y, 0.f); }
                if (mz)   { o.x = 0.f; o.y = 0.f; }
                if (OUTHALF) {
                    __half2* crow = reinterpret_cast<__half2*>((__half*)Cv + (size_t)row * N + col);
                    *crow = __float22half2_rn(o);
                } else {
                    float* crow = (float*)Cv + (size_t)row * N + col;
                    *reinterpret_cast<float2*>(crow) = o;
                }
            }
        }
    }
}

// -------------------- elementwise add -----------------------------------------
__global__ void addq_kernel(const float* __restrict__ a, const float* __restrict__ b,
                            float* __restrict__ o, int n4) {
    int i = blockIdx.x * blockDim.x + threadIdx.x;
    if (i < n4) {
        float4 va = reinterpret_cast<const float4*>(a)[i];
        float4 vb = reinterpret_cast<const float4*>(b)[i];
        reinterpret_cast<float4*>(o)[i] = make_float4(va.x+vb.x, va.y+vb.y, va.z+vb.z, va.w+vb.w);
    }
}

// -------------------- softmax over 16 logits ----------------------------------
__global__ void softmax16_kernel(float* __restrict__ a, int rows) {
    int r = blockIdx.x * blockDim.x + threadIdx.x;
    if (r >= rows) return;
    float* p = a + (size_t)r * 16;
    float mx = -1e30f;
#pragma unroll
    for (int i = 0; i < 16; i++) mx = fmaxf(mx, p[i]);
    float s = 0.f, e[16];
#pragma unroll
    for (int i = 0; i < 16; i++) { e[i] = __expf(p[i] - mx); s += e[i]; }
    float inv = 1.f / s;
#pragma unroll
    for (int i = 0; i < 16; i++) p[i] = e[i] * inv;
}

// -------------------- deformable sampling: one warp per head ------------------
__global__ __launch_bounds__(256)
void sample_kernel(const float* __restrict__ ref_pts, const int* __restrict__ shapes,
                   const int* __restrict__ lsi, const float* __restrict__ off,
                   const float* __restrict__ attn, const __half* __restrict__ value,
                   float* __restrict__ acc, int qbase)
{
    int qid = qbase + blockIdx.x;
    int n   = qid >> 10;
    int h   = threadIdx.x >> 5;
    int d   = threadIdx.x & 31;

    const float* offp = off  + (size_t)qid * (NH*NL*NP*3) + h * (NL*NP*3);
    const float* awp  = attn + (size_t)qid * (NH*NL*NP)   + h * (NL*NP);
    const float* refp = ref_pts + (size_t)qid * (NL*3);
    const __half* vbase = value + ((size_t)n * LIN * NH + h) * HD + d;

    float a = 0.f;
#pragma unroll
    for (int l = 0; l < NL; l++) {
        int Tl = shapes[l*3+0], Hl = shapes[l*3+1], Wl = shapes[l*3+2];
        int start = lsi[l];
        float fT = (float)Tl, fH = (float)Hl, fW = (float)Wl;
        float r0 = refp[l*3+0], r1 = refp[l*3+1], r2 = refp[l*3+2];
#pragma unroll
        for (int p = 0; p < NP; p++) {
            float pt = (r0 + offp[(l*NP+p)*3+0] / fT) * fT - 0.5f;
            float py = (r1 + offp[(l*NP+p)*3+1] / fH) * fH - 0.5f;
            float px = (r2 + offp[(l*NP+p)*3+2] / fW) * fW - 0.5f;
            float t0f = floorf(pt), y0f = floorf(py), x0f = floorf(px);
            float ft = pt - t0f, fy = py - y0f, fx = px - x0f;
            int t0 = (int)t0f, y0 = (int)y0f, x0 = (int)x0f;
            float samp = 0.f;
#pragma unroll
            for (int dt = 0; dt < 2; dt++) {
                int it = t0 + dt;
                if (it < 0 || it >= Tl) continue;
                float wt = dt ? ft : (1.f - ft);
#pragma unroll
                for (int dy = 0; dy < 2; dy++) {
                    int iy = y0 + dy;
                    if (iy < 0 || iy >= Hl) continue;
                    float wty = wt * (dy ? fy : (1.f - fy));
#pragma unroll
                    for (int dx = 0; dx < 2; dx++) {
                        int ix = x0 + dx;
                        if (ix < 0 || ix >= Wl) continue;
                        float w = wty * (dx ? fx : (1.f - fx));
                        int idx = start + (it * Hl + iy) * Wl + ix;
                        samp += w * __half2float(vbase[(size_t)idx * (NH*HD)]);
                    }
                }
            }
            a += awp[l*NP+p] * samp;
        }
    }
    acc[(size_t)qid * DM + h * HD + d] = a;
}

// -------------------- LayerNorm (256) ------------------------------------------
__global__ __launch_bounds__(256)
void ln_kernel(const float* __restrict__ in, const float* __restrict__ g,
               const float* __restrict__ b, float* __restrict__ out)
{
    int row = blockIdx.x;
    int t = threadIdx.x;
    float v = in[(size_t)row * DM + t];
    float s = v, s2 = v * v;
#pragma unroll
    for (int o = 16; o > 0; o >>= 1) {
        s  += __shfl_down_sync(0xffffffffu, s, o);
        s2 += __shfl_down_sync(0xffffffffu, s2, o);
    }
    __shared__ float ws[8], ws2[8];
    if ((t & 31) == 0) { ws[t >> 5] = s; ws2[t >> 5] = s2; }
    __syncthreads();
    float S = 0.f, S2 = 0.f;
#pragma unroll
    for (int i = 0; i < 8; i++) { S += ws[i]; S2 += ws2[i]; }
    float m   = S * (1.f / DM);
    float var = S2 * (1.f / DM) - m * m;
    float inv = rsqrtf(var + 1e-5f);
    out[(size_t)row * DM + t] = (v - m) * inv * g[t] + b[t];
}

// -------------------- host launcher --------------------------------------------
#define NSPLIT 4

extern "C" void kernel_launch(void* const* d_in, const int* in_sizes, int n_in,
                              void* d_out, int out_size)
{
    const float* tgt       = (const float*)d_in[0];
    const float* query_pos = (const float*)d_in[1];
    const float* ref_pts   = (const float*)d_in[2];
    const float* src       = (const float*)d_in[3];
    const int*   shapes    = (const int*)d_in[4];
    const int*   lsi       = (const int*)d_in[5];
    const unsigned char* pad_mask = (const unsigned char*)d_in[6];
    const float* Wv  = (const float*)d_in[7];
    const float* bv  = (const float*)d_in[8];
    const float* Wo  = (const float*)d_in[9];
    const float* bo  = (const float*)d_in[10];
    const float* Wa  = (const float*)d_in[11];
    const float* ba  = (const float*)d_in[12];
    const float* Wp  = (const float*)d_in[13];
    const float* bp  = (const float*)d_in[14];
    const float* ln1g = (const float*)d_in[15];
    const float* ln1b = (const float*)d_in[16];
    const float* W1  = (const float*)d_in[17];
    const float* b1  = (const float*)d_in[18];
    const float* W2  = (const float*)d_in[19];
    const float* b2  = (const float*)d_in[20];
    const float* ln3g = (const float*)d_in[21];
    const float* ln3b = (const float*)d_in[22];
    float* out = (float*)d_out;

    float *q, *off, *attn, *acc, *t2, *x, *ff1, *y;
    __half *value, *wh;
    cudaGetSymbolAddress((void**)&q,     g_q);
    cudaGetSymbolAddress((void**)&value, g_value);
    cudaGetSymbolAddress((void**)&off,   g_off);
    cudaGetSymbolAddress((void**)&attn,  g_attn);
    cudaGetSymbolAddress((void**)&acc,   g_acc);
    cudaGetSymbolAddress((void**)&t2,    g_t2);
    cudaGetSymbolAddress((void**)&x,     g_x);
    cudaGetSymbolAddress((void**)&ff1,   g_ff1);
    cudaGetSymbolAddress((void**)&y,     g_y);
    cudaGetSymbolAddress((void**)&wh,    g_wh);

    cudaFuncSetAttribute(mma_gemm<0,0>, cudaFuncAttributeMaxDynamicSharedMemorySize, SMEM_BYTES);
    cudaFuncSetAttribute(mma_gemm<1,0>, cudaFuncAttributeMaxDynamicSharedMemorySize, SMEM_BYTES);
    cudaFuncSetAttribute(mma_gemm<0,1>, cudaFuncAttributeMaxDynamicSharedMemorySize, SMEM_BYTES);

    static cudaStream_t s1 = nullptr;
    static cudaEvent_t evW = nullptr, evQ = nullptr, evT1 = nullptr;
    static cudaEvent_t evV[NSPLIT];
    if (s1 == nullptr) {
        cudaStreamCreateWithFlags(&s1, cudaStreamNonBlocking);
        cudaEventCreateWithFlags(&evW,  cudaEventDisableTiming);
        cudaEventCreateWithFlags(&evQ,  cudaEventDisableTiming);
        cudaEventCreateWithFlags(&evT1, cudaEventDisableTiming);
        for (int i = 0; i < NSPLIT; i++)
            cudaEventCreateWithFlags(&evV[i], cudaEventDisableTiming);
    }

    const int MQ = NV / NSPLIT;   // 87040 value rows per quarter
    const int QQ = NQ / NSPLIT;   // 2048 queries per quarter

    // ---- Wv permute first: it alone gates the value-GEMM fork ----
    permute_wh<<<256, 256>>>(Wv, wh + WT_V, 256, 256);
    cudaEventRecord(evW, 0);

    // ---- s1: value projection in 4 quarters ----
    cudaStreamWaitEvent(s1, evW, 0);
    for (int i = 0; i < NSPLIT; i++) {
        mma_gemm<0,1><<<dim3(2, MQ/128), 256, SMEM_BYTES, s1>>>(
            src + (size_t)i * MQ * DM, wh + WT_V, bv, nullptr,
            pad_mask + (size_t)i * MQ,
            value + (size_t)i * MQ * DM, MQ, 256, 256);
        cudaEventRecord(evV[i], s1);
    }

    // ---- main: remaining permutes + query prologue (overlaps value GEMM) ----
    permute_wh<<<384,  256>>>(Wo, wh + WT_O, 256, 384);
    permute_wh<<<128,  256>>>(Wa, wh + WT_A, 256, 128);
    permute_wh<<<256,  256>>>(Wp, wh + WT_P, 256, 256);
    permute_wh<<<1024, 256>>>(W1, wh + WT_1, 256, 1024);
    permute_wh<<<1024, 256>>>(W2, wh + WT_2, 1024, 256);
    addq_kernel<<<(NQ*DM/4 + 255)/256, 256>>>(tgt, query_pos, q, NQ*DM/4);
    mma_gemm<0,0><<<dim3(3, NQ/128), 256, SMEM_BYTES>>>(q, wh + WT_O, bo, nullptr, nullptr, off, NQ, 384, 256);
    mma_gemm<0,0><<<dim3(1, NQ/128), 256, SMEM_BYTES>>>(q, wh + WT_A, ba, nullptr, nullptr, attn, NQ, 128, 256);
    softmax16_kernel<<<(NQ*NH + 255)/256, 256>>>(attn, NQ*NH);
    cudaEventRecord(evQ, 0);

    // ---- per-quarter sample+tail pipelines: q0-q2 on main, q3 on s1 ----
    for (int i = 0; i < NSPLIT - 1; i++) {
        const size_t rQ = (size_t)i * QQ * DM;
        const size_t rF = (size_t)i * QQ * DFF;
        cudaStreamWaitEvent(0, evV[i], 0);
        sample_kernel<<<QQ, 256>>>(ref_pts, shapes, lsi, off, attn, value, acc, i * QQ);
        mma_gemm<0,0><<<dim3(2, QQ/128), 256, SMEM_BYTES>>>(
            acc + rQ, wh + WT_P, bp, tgt + rQ, nullptr, t2 + rQ, QQ, 256, 256);
        ln_kernel<<<QQ, 256>>>(t2 + rQ, ln1g, ln1b, x + rQ);
        mma_gemm<1,0><<<dim3(8, QQ/128), 256, SMEM_BYTES>>>(
            x + rQ, wh + WT_1, b1, nullptr, nullptr, ff1 + rF, QQ, 1024, 256);
        mma_gemm<0,0><<<dim3(2, QQ/128), 256, SMEM_BYTES>>>(
            ff1 + rF, wh + WT_2, b2, x + rQ, nullptr, y + rQ, QQ, 256, 1024);
        ln_kernel<<<QQ, 256>>>(y + rQ, ln3g, ln3b, out + rQ);
    }

    // quarter 3 on s1 (after V3 in-order; needs query prologue + permutes)
    {
        const int i = NSPLIT - 1;
        const size_t rQ = (size_t)i * QQ * DM;
        const size_t rF = (size_t)i * QQ * DFF;
        cudaStreamWaitEvent(s1, evQ, 0);
        sample_kernel<<<QQ, 256, 0, s1>>>(ref_pts, shapes, lsi, off, attn, value, acc, i * QQ);
        mma_gemm<0,0><<<dim3(2, QQ/128), 256, SMEM_BYTES, s1>>>(
            acc + rQ, wh + WT_P, bp, tgt + rQ, nullptr, t2 + rQ, QQ, 256, 256);
        ln_kernel<<<QQ, 256, 0, s1>>>(t2 + rQ, ln1g, ln1b, x + rQ);
        mma_gemm<1,0><<<dim3(8, QQ/128), 256, SMEM_BYTES, s1>>>(
            x + rQ, wh + WT_1, b1, nullptr, nullptr, ff1 + rF, QQ, 1024, 256);
        mma_gemm<0,0><<<dim3(2, QQ/128), 256, SMEM_BYTES, s1>>>(
            ff1 + rF, wh + WT_2, b2, x + rQ, nullptr, y + rQ, QQ, 256, 1024);
        ln_kernel<<<QQ, 256, 0, s1>>>(y + rQ, ln3g, ln3b, out + rQ);
        cudaEventRecord(evT1, s1);
    }

    // ---- join ----
    cudaStreamWaitEvent(0, evT1, 0);
}

// round 17
// speedup vs baseline: 1.3544x; 1.3544x over previous
#include <cuda_runtime.h>
#include <cuda_fp16.h>
#include <cstdint>

// Problem constants (fixed by the dataset)
#define NB   8
#define LQ   1024
#define NQ   (NB*LQ)        // 8192
#define DM   256
#define DFF  1024
#define NH   8
#define HD   32
#define NL   4
#define NP   4
#define LIN  43520
#define NV   (NB*LIN)       // 348160

// -------------------- scratch (device globals) -------------------------------
__device__ float  g_q   [(size_t)NQ*DM];
__device__ __half g_value[(size_t)NV*DM];      // fp16 value (178 MB)
__device__ float  g_off [(size_t)NQ*NH*NL*NP*3];
__device__ float  g_attn[(size_t)NQ*NH*NL*NP];
__device__ float  g_acc [(size_t)NQ*DM];
__device__ float  g_t2  [(size_t)NQ*DM];
__device__ float  g_x   [(size_t)NQ*DM];
__device__ float  g_ff1 [(size_t)NQ*DFF];
__device__ float  g_y   [(size_t)NQ*DM];
__device__ __half g_wh  [786432];   // permuted fp16 weights

#define WT_V 0
#define WT_O 65536
#define WT_A 163840
#define WT_P 196608
#define WT_1 262144
#define WT_2 524288

// -------------------- smem layout: 128x128 tile, 3 stages ----------------------
// A: fp32, 128 rows x 32 k, stride 36 floats. B: fp16, 128 n-rows x 32 k', dense.
#define A_STRIDE 36
#define ABUF (128 * A_STRIDE)              // 4608 floats / stage
#define NSTAGE 3
#define A_BYTES (NSTAGE * ABUF * 4)        // 55296
#define B_STG_BYTES (128 * 32 * 2)         // 8192 / stage
#define SMEM_BYTES (A_BYTES + NSTAGE * B_STG_BYTES)   // 79872

__device__ __forceinline__ uint32_t smem_to_u32(const void* p) {
    uint32_t a;
    asm("{ .reg .u64 t; cvta.to.shared.u64 t, %1; cvt.u32.u64 %0, t; }" : "=r"(a) : "l"(p));
    return a;
}

#define CP_ASYNC16(saddr, gaddr) \
    asm volatile("cp.async.cg.shared.global [%0], [%1], 16;" :: "r"(saddr), "l"(gaddr))
#define CP_COMMIT() asm volatile("cp.async.commit_group;" ::: "memory")
#define CP_WAIT1()  asm volatile("cp.async.wait_group 1;" ::: "memory")
#define CP_WAIT0()  asm volatile("cp.async.wait_group 0;" ::: "memory")

#define MMA_F16(d, a, b0, b1) \
    asm volatile("mma.sync.aligned.m16n8k16.row.col.f32.f16.f16.f32 " \
        "{%0,%1,%2,%3}, {%4,%5,%6,%7}, {%8,%9}, {%0,%1,%2,%3};" \
        : "+f"((d)[0]), "+f"((d)[1]), "+f"((d)[2]), "+f"((d)[3]) \
        : "r"((a)[0]), "r"((a)[1]), "r"((a)[2]), "r"((a)[3]), "r"(b0), "r"(b1))

__device__ __forceinline__ uint32_t f22h2(float2 v) {
    __half2 h = __float22half2_rn(v);
    return *reinterpret_cast<uint32_t*>(&h);
}

// -------------------- weight permute (fp32 -> fp16, m16n8k16 B order) ----------
// Within each 32-k chunk, position p = tg*8 + u maps to
// k = 2*tg + (u&1) + 8*((u>>1)&1) + 16*(u>>2)
// so one LDS.128 at half-offset tg*8 yields {b0,b1} for both k16 steps.
__global__ void permute_wh(const float* __restrict__ W, __half* __restrict__ Wp,
                           int K, int N)
{
    int i = blockIdx.x * 256 + threadIdx.x;
    if (i >= N * K) return;
    int n = i / K, r = i - n * K;
    int kc = r >> 5, p = r & 31;
    int tg = p >> 3, u = p & 7;
    int k = kc * 32 + 2 * tg + (u & 1) + 8 * ((u >> 1) & 1) + 16 * (u >> 2);
    Wp[i] = __float2half(W[(size_t)k * N + n]);
}

// -------------------- FP16 tensor-core GEMM, 128x128 tile, 3-stage -------------
// C[M,N] = A[M,K] @ W[K,N] + bias (+resid) (relu?) (mask -> zero row)
// OUTHALF: C is __half*, else float*. A fp32, Wp permuted fp16.
// Grid: (N/128, M/128). 256 threads. K % 32 == 0, K >= 64.
template<int RELU, int OUTHALF>
__global__ __launch_bounds__(256, 2)
void mma_gemm(const float* __restrict__ A, const __half* __restrict__ Wp,
              const float* __restrict__ bias, const float* __restrict__ resid,
              const unsigned char* __restrict__ mask,
              void* __restrict__ Cv, int M, int N, int K)
{
    extern __shared__ float sm[];
    uint32_t sb = smem_to_u32(sm);
    const int tid  = threadIdx.x;
    const int wid  = tid >> 5, lane = tid & 31;
    const int g    = lane >> 2, tg = lane & 3;
    const int mw   = wid & 3,  nw = wid >> 2;   // 4 m-warps x 2 n-warps
    const int m0   = blockIdx.y * 128;
    const int n0   = blockIdx.x * 128;
    const int nK   = K >> 5;

    float d[2][8][4];
#pragma unroll
    for (int mi = 0; mi < 2; mi++)
#pragma unroll
        for (int nj = 0; nj < 8; nj++)
#pragma unroll
            for (int r = 0; r < 4; r++) d[mi][nj][r] = 0.f;

    auto load_chunk = [&](int kc, int stage) {
        const char* Ag = (const char*)(A + (size_t)m0 * K + (size_t)kc * 32);
#pragma unroll
        for (int i = 0; i < 4; i++) {
            int u = tid + i * 256;
            int row = u >> 3, seg = u & 7;
            uint32_t sa = sb + (uint32_t)(stage * ABUF + row * A_STRIDE + seg * 4) * 4;
            CP_ASYNC16(sa, Ag + ((size_t)row * K + seg * 4) * 4);
        }
        const char* Wg = (const char*)(Wp + (size_t)n0 * K + (size_t)kc * 32);
#pragma unroll
        for (int i = 0; i < 2; i++) {
            int u = tid + i * 256;
            int row = u >> 2, seg = u & 3;
            uint32_t sa = sb + (uint32_t)A_BYTES + (uint32_t)(stage * B_STG_BYTES + row * 64 + seg * 16);
            CP_ASYNC16(sa, Wg + (size_t)row * K * 2 + seg * 16);
        }
        CP_COMMIT();
    };

    load_chunk(0, 0);
    load_chunk(1, 1);

    int stage = 0;
    for (int kc = 0; kc < nK; kc++) {
        if (kc == nK - 1) { CP_WAIT0(); } else { CP_WAIT1(); }
        __syncthreads();
        // prefetch chunk kc+2 into the stage last read at kc-1 (all warps past it)
        if (kc + 2 < nK) {
            int ns = stage + 2; if (ns >= NSTAGE) ns -= NSTAGE;
            load_chunk(kc + 2, ns);
        }

        const float* Asb = sm + stage * ABUF;
        const __half* Bsb = reinterpret_cast<const __half*>(
            (const char*)sm + A_BYTES + stage * B_STG_BYTES);

        // B fragments: one LDS.128 per nj covers both k16 steps
        // .x = b0(ks0), .y = b1(ks0), .z = b0(ks1), .w = b1(ks1)
        uint4 bq[8];
#pragma unroll
        for (int nj = 0; nj < 8; nj++)
            bq[nj] = *reinterpret_cast<const uint4*>(
                Bsb + (nw * 64 + nj * 8 + g) * 32 + tg * 8);

#pragma unroll
        for (int ks = 0; ks < 2; ks++) {
            uint32_t a[2][4];
#pragma unroll
            for (int mi = 0; mi < 2; mi++) {
                const float* ap = Asb + (mw * 32 + mi * 16 + g) * A_STRIDE + ks * 16 + 2 * tg;
                a[mi][0] = f22h2(*reinterpret_cast<const float2*>(ap));
                a[mi][1] = f22h2(*reinterpret_cast<const float2*>(ap + 8 * A_STRIDE));
                a[mi][2] = f22h2(*reinterpret_cast<const float2*>(ap + 8));
                a[mi][3] = f22h2(*reinterpret_cast<const float2*>(ap + 8 * A_STRIDE + 8));
            }
#pragma unroll
            for (int nj = 0; nj < 8; nj++) {
                uint32_t b0 = ks ? bq[nj].z : bq[nj].x;
                uint32_t b1 = ks ? bq[nj].w : bq[nj].y;
                MMA_F16(d[0][nj], a[0], b0, b1);
                MMA_F16(d[1][nj], a[1], b0, b1);
            }
        }
        stage = (stage + 1 == NSTAGE) ? 0 : stage + 1;
    }

    // ---- epilogue ----
#pragma unroll
    for (int mi = 0; mi < 2; mi++) {
#pragma unroll
        for (int half = 0; half < 2; half++) {
            const int row = m0 + mw * 32 + mi * 16 + g + half * 8;
            const bool mz = (mask != nullptr) && mask[row];
            const float* rrow = resid ? (resid + (size_t)row * N) : nullptr;
#pragma unroll
            for (int nj = 0; nj < 8; nj++) {
                const int col = n0 + nw * 64 + nj * 8 + 2 * tg;
                float2 o;
                o.x = d[mi][nj][half * 2 + 0] + bias[col];
                o.y = d[mi][nj][half * 2 + 1] + bias[col + 1];
                if (rrow) {
                    float2 rv = *reinterpret_cast<const float2*>(rrow + col);
                    o.x += rv.x; o.y += rv.y;
                }
                if (RELU) { o.x = fmaxf(o.x, 0.f); o.y = fmaxf(o.y, 0.f); }
                if (mz)   { o.x = 0.f; o.y = 0.f; }
                if (OUTHALF) {
                    __half2* crow = reinterpret_cast<__half2*>((__half*)Cv + (size_t)row * N + col);
                    *crow = __float22half2_rn(o);
                } else {
                    float* crow = (float*)Cv + (size_t)row * N + col;
                    *reinterpret_cast<float2*>(crow) = o;
                }
            }
        }
    }
}

// -------------------- elementwise add -----------------------------------------
__global__ void addq_kernel(const float* __restrict__ a, const float* __restrict__ b,
                            float* __restrict__ o, int n4) {
    int i = blockIdx.x * blockDim.x + threadIdx.x;
    if (i < n4) {
        float4 va = reinterpret_cast<const float4*>(a)[i];
        float4 vb = reinterpret_cast<const float4*>(b)[i];
        reinterpret_cast<float4*>(o)[i] = make_float4(va.x+vb.x, va.y+vb.y, va.z+vb.z, va.w+vb.w);
    }
}

// -------------------- softmax over 16 logits ----------------------------------
__global__ void softmax16_kernel(float* __restrict__ a, int rows) {
    int r = blockIdx.x * blockDim.x + threadIdx.x;
    if (r >= rows) return;
    float* p = a + (size_t)r * 16;
    float mx = -1e30f;
#pragma unroll
    for (int i = 0; i < 16; i++) mx = fmaxf(mx, p[i]);
    float s = 0.f, e[16];
#pragma unroll
    for (int i = 0; i < 16; i++) { e[i] = __expf(p[i] - mx); s += e[i]; }
    float inv = 1.f / s;
#pragma unroll
    for (int i = 0; i < 16; i++) p[i] = e[i] * inv;
}

// -------------------- deformable sampling: one warp per 2 heads ----------------
// Block = 256 threads = 8 warps = 2 queries (4 warps each).
// Warp covers heads {2hp, 2hp+1}: lanes 0-15 -> head 2hp, lanes 16-31 -> head 2hp+1.
// Each lane handles dims (2dp, 2dp+1) via __half2. Per-element math order identical
// to the one-warp-per-head version (same corner order) -> bit-identical results.
__global__ __launch_bounds__(256)
void sample_kernel(const float* __restrict__ ref_pts, const int* __restrict__ shapes,
                   const int* __restrict__ lsi, const float* __restrict__ off,
                   const float* __restrict__ attn, const __half* __restrict__ value,
                   float* __restrict__ acc, int qbase)
{
    const int wid  = threadIdx.x >> 5;
    const int lane = threadIdx.x & 31;
    const int qid  = qbase + blockIdx.x * 2 + (wid >> 2);
    const int n    = qid >> 10;
    const int h    = ((wid & 3) << 1) + (lane >> 4);   // head 0..7
    const int dp   = lane & 15;                         // dim-pair 0..15

    const float* offp = off  + (size_t)qid * (NH*NL*NP*3) + h * (NL*NP*3);
    const float* awp  = attn + (size_t)qid * (NH*NL*NP)   + h * (NL*NP);
    const float* refp = ref_pts + (size_t)qid * (NL*3);
    const __half2* vbase = reinterpret_cast<const __half2*>(
        value + ((size_t)n * LIN * NH + h) * HD) + dp;

    float ax = 0.f, ay = 0.f;
#pragma unroll
    for (int l = 0; l < NL; l++) {
        int Tl = shapes[l*3+0], Hl = shapes[l*3+1], Wl = shapes[l*3+2];
        int start = lsi[l];
        float fT = (float)Tl, fH = (float)Hl, fW = (float)Wl;
        float r0 = refp[l*3+0], r1 = refp[l*3+1], r2 = refp[l*3+2];
#pragma unroll
        for (int p = 0; p < NP; p++) {
            float pt = (r0 + offp[(l*NP+p)*3+0] / fT) * fT - 0.5f;
            float py = (r1 + offp[(l*NP+p)*3+1] / fH) * fH - 0.5f;
            float px = (r2 + offp[(l*NP+p)*3+2] / fW) * fW - 0.5f;
            float t0f = floorf(pt), y0f = floorf(py), x0f = floorf(px);
            float ft = pt - t0f, fy = py - y0f, fx = px - x0f;
            int t0 = (int)t0f, y0 = (int)y0f, x0 = (int)x0f;
            float sx = 0.f, sy = 0.f;
#pragma unroll
            for (int dt = 0; dt < 2; dt++) {
                int it = t0 + dt;
                if (it < 0 || it >= Tl) continue;
                float wt = dt ? ft : (1.f - ft);
#pragma unroll
                for (int dy = 0; dy < 2; dy++) {
                    int iy = y0 + dy;
                    if (iy < 0 || iy >= Hl) continue;
                    float wty = wt * (dy ? fy : (1.f - fy));
#pragma unroll
                    for (int dx = 0; dx < 2; dx++) {
                        int ix = x0 + dx;
                        if (ix < 0 || ix >= Wl) continue;
                        float w = wty * (dx ? fx : (1.f - fx));
                        int idx = start + (it * Hl + iy) * Wl + ix;
                        float2 fv = __half22float2(vbase[(size_t)idx * (NH*HD/2)]);
                        sx += w * fv.x;
                        sy += w * fv.y;
                    }
                }
            }
            float aw = awp[l*NP+p];
            ax += aw * sx;
            ay += aw * sy;
        }
    }
    float2* op = reinterpret_cast<float2*>(acc + (size_t)qid * DM + h * HD + 2 * dp);
    *op = make_float2(ax, ay);
}

// -------------------- LayerNorm (256) ------------------------------------------
__global__ __launch_bounds__(256)
void ln_kernel(const float* __restrict__ in, const float* __restrict__ g,
               const float* __restrict__ b, float* __restrict__ out)
{
    int row = blockIdx.x;
    int t = threadIdx.x;
    float v = in[(size_t)row * DM + t];
    float s = v, s2 = v * v;
#pragma unroll
    for (int o = 16; o > 0; o >>= 1) {
        s  += __shfl_down_sync(0xffffffffu, s, o);
        s2 += __shfl_down_sync(0xffffffffu, s2, o);
    }
    __shared__ float ws[8], ws2[8];
    if ((t & 31) == 0) { ws[t >> 5] = s; ws2[t >> 5] = s2; }
    __syncthreads();
    float S = 0.f, S2 = 0.f;
#pragma unroll
    for (int i = 0; i < 8; i++) { S += ws[i]; S2 += ws2[i]; }
    float m   = S * (1.f / DM);
    float var = S2 * (1.f / DM) - m * m;
    float inv = rsqrtf(var + 1e-5f);
    out[(size_t)row * DM + t] = (v - m) * inv * g[t] + b[t];
}

// -------------------- host launcher --------------------------------------------
extern "C" void kernel_launch(void* const* d_in, const int* in_sizes, int n_in,
                              void* d_out, int out_size)
{
    const float* tgt       = (const float*)d_in[0];
    const float* query_pos = (const float*)d_in[1];
    const float* ref_pts   = (const float*)d_in[2];
    const float* src       = (const float*)d_in[3];
    const int*   shapes    = (const int*)d_in[4];
    const int*   lsi       = (const int*)d_in[5];
    const unsigned char* pad_mask = (const unsigned char*)d_in[6];
    const float* Wv  = (const float*)d_in[7];
    const float* bv  = (const float*)d_in[8];
    const float* Wo  = (const float*)d_in[9];
    const float* bo  = (const float*)d_in[10];
    const float* Wa  = (const float*)d_in[11];
    const float* ba  = (const float*)d_in[12];
    const float* Wp  = (const float*)d_in[13];
    const float* bp  = (const float*)d_in[14];
    const float* ln1g = (const float*)d_in[15];
    const float* ln1b = (const float*)d_in[16];
    const float* W1  = (const float*)d_in[17];
    const float* b1  = (const float*)d_in[18];
    const float* W2  = (const float*)d_in[19];
    const float* b2  = (const float*)d_in[20];
    const float* ln3g = (const float*)d_in[21];
    const float* ln3b = (const float*)d_in[22];
    float* out = (float*)d_out;

    float *q, *off, *attn, *acc, *t2, *x, *ff1, *y;
    __half *value, *wh;
    cudaGetSymbolAddress((void**)&q,     g_q);
    cudaGetSymbolAddress((void**)&value, g_value);
    cudaGetSymbolAddress((void**)&off,   g_off);
    cudaGetSymbolAddress((void**)&attn,  g_attn);
    cudaGetSymbolAddress((void**)&acc,   g_acc);
    cudaGetSymbolAddress((void**)&t2,    g_t2);
    cudaGetSymbolAddress((void**)&x,     g_x);
    cudaGetSymbolAddress((void**)&ff1,   g_ff1);
    cudaGetSymbolAddress((void**)&y,     g_y);
    cudaGetSymbolAddress((void**)&wh,    g_wh);

    cudaFuncSetAttribute(mma_gemm<0,0>, cudaFuncAttributeMaxDynamicSharedMemorySize, SMEM_BYTES);
    cudaFuncSetAttribute(mma_gemm<1,0>, cudaFuncAttributeMaxDynamicSharedMemorySize, SMEM_BYTES);
    cudaFuncSetAttribute(mma_gemm<0,1>, cudaFuncAttributeMaxDynamicSharedMemorySize, SMEM_BYTES);

    static cudaStream_t s1 = nullptr;
    static cudaEvent_t evW = nullptr, evV0 = nullptr, evQ = nullptr, evT1 = nullptr;
    if (s1 == nullptr) {
        cudaStreamCreateWithFlags(&s1, cudaStreamNonBlocking);
        cudaEventCreateWithFlags(&evW,  cudaEventDisableTiming);
        cudaEventCreateWithFlags(&evV0, cudaEventDisableTiming);
        cudaEventCreateWithFlags(&evQ,  cudaEventDisableTiming);
        cudaEventCreateWithFlags(&evT1, cudaEventDisableTiming);
    }

    const int MH = NV / 2;   // value rows per half
    const int QH = NQ / 2;   // query rows per half

    // ---- Wv permute first: it alone gates the value-GEMM fork ----
    permute_wh<<<256, 256>>>(Wv, wh + WT_V, 256, 256);
    cudaEventRecord(evW, 0);

    // ---- s1: value projection (2 halves, fp16 output) ----
    cudaStreamWaitEvent(s1, evW, 0);
    mma_gemm<0,1><<<dim3(2, MH/128), 256, SMEM_BYTES, s1>>>(
        src, wh + WT_V, bv, nullptr, pad_mask, value, MH, 256, 256);
    cudaEventRecord(evV0, s1);
    mma_gemm<0,1><<<dim3(2, MH/128), 256, SMEM_BYTES, s1>>>(
        src + (size_t)MH * DM, wh + WT_V, bv, nullptr, pad_mask + MH,
        value + (size_t)MH * DM, MH, 256, 256);

    // ---- main: remaining permutes + query prologue (overlaps value GEMM) ----
    permute_wh<<<384,  256>>>(Wo, wh + WT_O, 256, 384);
    permute_wh<<<128,  256>>>(Wa, wh + WT_A, 256, 128);
    permute_wh<<<256,  256>>>(Wp, wh + WT_P, 256, 256);
    permute_wh<<<1024, 256>>>(W1, wh + WT_1, 256, 1024);
    permute_wh<<<1024, 256>>>(W2, wh + WT_2, 1024, 256);
    addq_kernel<<<(NQ*DM/4 + 255)/256, 256>>>(tgt, query_pos, q, NQ*DM/4);
    mma_gemm<0,0><<<dim3(3, NQ/128), 256, SMEM_BYTES>>>(q, wh + WT_O, bo, nullptr, nullptr, off, NQ, 384, 256);
    mma_gemm<0,0><<<dim3(1, NQ/128), 256, SMEM_BYTES>>>(q, wh + WT_A, ba, nullptr, nullptr, attn, NQ, 128, 256);
    softmax16_kernel<<<(NQ*NH + 255)/256, 256>>>(attn, NQ*NH);
    cudaEventRecord(evQ, 0);

    // ---- per-half pipelines: half 0 on main, half 1 on s1 ----
    // half 0 (main): waits value half 0
    cudaStreamWaitEvent(0, evV0, 0);
    sample_kernel<<<QH/2, 256>>>(ref_pts, shapes, lsi, off, attn, value, acc, 0);
    mma_gemm<0,0><<<dim3(2, QH/128), 256, SMEM_BYTES>>>(acc, wh + WT_P, bp, tgt, nullptr, t2, QH, 256, 256);
    ln_kernel<<<QH, 256>>>(t2, ln1g, ln1b, x);
    mma_gemm<1,0><<<dim3(8, QH/128), 256, SMEM_BYTES>>>(x, wh + WT_1, b1, nullptr, nullptr, ff1, QH, 1024, 256);
    mma_gemm<0,0><<<dim3(2, QH/128), 256, SMEM_BYTES>>>(ff1, wh + WT_2, b2, x, nullptr, y, QH, 256, 1024);
    ln_kernel<<<QH, 256>>>(y, ln3g, ln3b, out);

    // half 1 (s1): runs after value half 1 (in-order on s1) + query prologue
    {
        const size_t rQ = (size_t)QH * DM;    // row offset (DM-wide arrays)
        const size_t rF = (size_t)QH * DFF;   // row offset (DFF-wide arrays)
        cudaStreamWaitEvent(s1, evQ, 0);
        sample_kernel<<<QH/2, 256, 0, s1>>>(ref_pts, shapes, lsi, off, attn, value, acc, QH);
        mma_gemm<0,0><<<dim3(2, QH/128), 256, SMEM_BYTES, s1>>>(
            acc + rQ, wh + WT_P, bp, tgt + rQ, nullptr, t2 + rQ, QH, 256, 256);
        ln_kernel<<<QH, 256, 0, s1>>>(t2 + rQ, ln1g, ln1b, x + rQ);
        mma_gemm<1,0><<<dim3(8, QH/128), 256, SMEM_BYTES, s1>>>(
            x + rQ, wh + WT_1, b1, nullptr, nullptr, ff1 + rF, QH, 1024, 256);
        mma_gemm<0,0><<<dim3(2, QH/128), 256, SMEM_BYTES, s1>>>(
            ff1 + rF, wh + WT_2, b2, x + rQ, nullptr, y + rQ, QH, 256, 1024);
        ln_kernel<<<QH, 256, 0, s1>>>(y + rQ, ln3g, ln3b, out + rQ);
        cudaEventRecord(evT1, s1);
    }

    // ---- join ----
    cudaStreamWaitEvent(0, evT1, 0);
}